// round 7
// baseline (speedup 1.0000x reference)
#include <cuda_runtime.h>
#include <cuda_fp16.h>
#include <cstdint>

// fp16 2-pass "exact-A" tensor-core version (mma.sync m16n8k16 f16, sm_80 PTX).
//   X[128x128] = [features2[topk] | features1]  (8 queries x 16 nbrs = 128 rows)
//   H = ELU(X@W1+b1); Y = ELU(H@W2+b2); out[q] = sum_k w[q,k] * Y[q*16+k]
// GEMM: D(fp32) = Xh*Wh + Xl*Wh = (Xh+Xl)*Wh = X*Wh  (A exact; err = W fp16 rounding)

namespace {
constexpr int kN1      = 50000;
constexpr int kNN      = 16;
constexpr int kQPB     = 8;
constexpr int kTiles   = kN1 / kQPB;   // 6250
constexpr int kThreads = 256;
constexpr int kGrid    = 148;

// SMEM byte offsets
constexpr int SM_ROWW  = 0;            // 128 f32
constexpr int SM_B1    = 512;          // 128 f32
constexpr int SM_B2    = 1024;         // 128 f32
constexpr int SM_X     = 2048;         // 128 rows x 256 fp16 (kk<128: hi, >=128: lo)
constexpr int SM_W     = SM_X + 128 * 512;       // 67584; 2 layers x 32768 B
constexpr int SM_WSZ   = 32768;
constexpr int SM_TOTAL = SM_W + 2 * SM_WSZ;      // 133120 B
}

// fp16 weights, transposed+swizzled: [W1, W2], each [n][k]
__device__ __align__(16) unsigned char g_Wh[2 * SM_WSZ];

// X tile: row stride 512 B, XOR swizzle on 16B groups within 128B lines
__device__ __forceinline__ uint32_t soff(int r, int kk) {
    return (uint32_t)(r * 512 + (((kk >> 3) ^ (r & 7)) << 4) + (kk & 7) * 2);
}
// W tile: row stride 256 B
__device__ __forceinline__ uint32_t woff(int n, int k) {
    return (uint32_t)(n * 256 + (((k >> 3) ^ (n & 7)) << 4) + (k & 7) * 2);
}

__device__ __forceinline__ uint32_t smem_u32(const void* p) {
    uint32_t a;
    asm("{ .reg .u64 t; cvta.to.shared.u64 t, %1; cvt.u32.u64 %0, t; }"
        : "=r"(a) : "l"(p));
    return a;
}
__device__ __forceinline__ void ldsm_x4(uint32_t* r, uint32_t addr) {
    asm volatile("ldmatrix.sync.aligned.m8n8.x4.shared.b16 {%0,%1,%2,%3}, [%4];"
                 : "=r"(r[0]), "=r"(r[1]), "=r"(r[2]), "=r"(r[3]) : "r"(addr));
}
__device__ __forceinline__ void mma16816(float* d, const uint32_t* a,
                                         const uint32_t* b) {
    asm volatile(
        "mma.sync.aligned.m16n8k16.row.col.f32.f16.f16.f32 "
        "{%0,%1,%2,%3}, {%4,%5,%6,%7}, {%8,%9}, {%0,%1,%2,%3};"
        : "+f"(d[0]), "+f"(d[1]), "+f"(d[2]), "+f"(d[3])
        : "r"(a[0]), "r"(a[1]), "r"(a[2]), "r"(a[3]), "r"(b[0]), "r"(b[1]));
}
__device__ __forceinline__ float elu_f(float x) {
    return x > 0.0f ? x : (__expf(x) - 1.0f);
}
// exact fp16 hi/lo split of a float pair -> two packed half2
__device__ __forceinline__ void split_h2(float a, float b, uint32_t& hi,
                                         uint32_t& lo) {
    const __half ah = __float2half_rn(a);
    const __half bh = __float2half_rn(b);
    __half2 h2 = __halves2half2(ah, bh);
    __half2 l2 = __halves2half2(__float2half_rn(a - __half2float(ah)),
                                __float2half_rn(b - __half2float(bh)));
    hi = *(uint32_t*)&h2;
    lo = *(uint32_t*)&l2;
}

// ---------------- W prep kernel ----------------
__global__ void prep_w_kernel(const float* __restrict__ W1,
                              const float* __restrict__ W2) {
    int idx = blockIdx.x * blockDim.x + threadIdx.x;   // 0 .. 32767
    if (idx >= 2 * 128 * 128) return;
    int l = idx >> 14;
    int e = idx & 16383;
    int n = e >> 7;      // output channel (B row)
    int k = e & 127;     // contraction
    const float* W = l ? W2 : W1;
    float v = W[k * 128 + n];                       // B[n][k] = W[k][n]
    *(__half*)(g_Wh + l * SM_WSZ + woff(n, k)) = __float2half_rn(v);
}

// issue the gather LDGs for one tile into registers
__device__ __forceinline__ void gather_regs(int tile, int tid, bool is64,
                                            const float* __restrict__ f1,
                                            const float* __restrict__ f2,
                                            const void* __restrict__ topk,
                                            float4 pf[8][2]) {
    const int qb = tile * kQPB;
    const int g  = tid & 15;           // 8-float group per row
    #pragma unroll
    for (int it = 0; it < 8; ++it) {
        const int rr = (tid >> 4) + it * 16;       // row 0..127
        const int q  = qb + (rr >> 4);
        const float4* p;
        if (g < 8) {
            const int nb = rr & 15;
            const int gi = is64 ? (int)((const long long*)topk)[q * kNN + nb]
                                : ((const int*)topk)[q * kNN + nb];
            p = (const float4*)(f2 + (size_t)gi * 64) + g * 2;
        } else {
            p = (const float4*)(f1 + (size_t)q * 64) + (g - 8) * 2;
        }
        pf[it][0] = p[0];
        pf[it][1] = p[1];
    }
}

// ---------------- main persistent kernel ----------------
__global__ void __launch_bounds__(kThreads, 1)
fused_mma_kernel(const float* __restrict__ f1, const float* __restrict__ f2,
                 const float* __restrict__ x1, const float* __restrict__ x2,
                 const void* __restrict__ topk,
                 const float* __restrict__ b1, const float* __restrict__ b2,
                 const float* __restrict__ radius, float* __restrict__ out)
{
    extern __shared__ char sm[];
    const uint32_t smb = smem_u32(sm);
    const int tid  = threadIdx.x;
    const int wid  = tid >> 5;
    const int lane = tid & 31;
    __shared__ int s_is64;

    // stage fp16 weights into SMEM once
    {
        const float4* src = (const float4*)g_Wh;
        float4* dst = (float4*)(sm + SM_W);
        #pragma unroll
        for (int i = 0; i < 16; i++) dst[tid + i * 256] = src[tid + i * 256];
    }
    if (tid < 128) {
        ((float*)(sm + SM_B1))[tid] = b1[tid];
        ((float*)(sm + SM_B2))[tid] = b2[tid];
    }
    if (tid < 32) {
        const int* t32 = (const int*)topk;
        unsigned m = __ballot_sync(0xFFFFFFFFu, t32[2 * tid + 1] != 0);
        if (tid == 0) s_is64 = (m == 0u) ? 1 : 0;
    }
    __syncthreads();

    const bool  is64 = (s_is64 != 0);
    const float r    = radius[0];
    const float nid  = -1.0f / (2.0f * r * r);

    const int wrow = (wid & 3) * 32;   // warp tile rows [wrow, wrow+32)
    const int wcol = (wid >> 2) * 64;  // warp tile cols [wcol, wcol+64)
    const int mat  = lane >> 3;        // ldmatrix sub-matrix index
    const int mrow = lane & 7;

    const uint32_t xb = smb + SM_X;

    // prologue: gather tile 0 (this CTA's first tile) into registers
    float4 pf[8][2];
    gather_regs(blockIdx.x, tid, is64, f1, f2, topk, pf);

    for (int tile = blockIdx.x; tile < kTiles; tile += gridDim.x) {
        const int qbase = tile * kQPB;

        __syncthreads();   // prev tile's layer-2 MMA done: X safe to overwrite

        // ---- convert prefetched registers -> Xhi/Xlo halves in smem ----
        {
            const int g = tid & 15;
            #pragma unroll
            for (int it = 0; it < 8; ++it) {
                const int rr = (tid >> 4) + it * 16;
                const float v[8] = {pf[it][0].x, pf[it][0].y, pf[it][0].z, pf[it][0].w,
                                    pf[it][1].x, pf[it][1].y, pf[it][1].z, pf[it][1].w};
                uint4 hi4, lo4;
                uint32_t* hp = (uint32_t*)&hi4;
                uint32_t* lp = (uint32_t*)&lo4;
                #pragma unroll
                for (int j = 0; j < 4; j++)
                    split_h2(v[2 * j], v[2 * j + 1], hp[j], lp[j]);
                *(uint4*)(sm + SM_X + soff(rr, g * 8))       = hi4;
                *(uint4*)(sm + SM_X + soff(rr, g * 8 + 128)) = lo4;
            }
        }
        // ---- per-row distance weights ----
        if (tid < 128) {
            const int q  = qbase + (tid >> 4);
            const int kk = tid & 15;
            int gi = is64 ? (int)((const long long*)topk)[q * kNN + kk]
                          : ((const int*)topk)[q * kNN + kk];
            const float dx = x2[gi * 3 + 0] - x1[q * 3 + 0];
            const float dy = x2[gi * 3 + 1] - x1[q * 3 + 1];
            const float dz = x2[gi * 3 + 2] - x1[q * 3 + 2];
            const float w  = __expf(nid * (dx * dx + dy * dy + dz * dz));
            ((float*)(sm + SM_ROWW))[tid] = (gi == 0) ? 0.0f : w;
        }
        __syncthreads();

        // ---- issue next tile's gather LDGs (hidden under MMA below) ----
        const int nxt = tile + gridDim.x;
        if (nxt < kTiles) gather_regs(nxt, tid, is64, f1, f2, topk, pf);

        float acc[2][8][4];
        #pragma unroll
        for (int i = 0; i < 2; i++)
            #pragma unroll
            for (int j = 0; j < 8; j++)
                #pragma unroll
                for (int e = 0; e < 4; e++) acc[i][j][e] = 0.0f;

        #pragma unroll 1
        for (int layer = 0; layer < 2; ++layer) {
            const uint32_t wb = smb + SM_W + layer * SM_WSZ;

            #pragma unroll 1
            for (int ks = 0; ks < 8; ++ks) {
                // B fragments once per ks, reused by both A halves
                uint32_t bfr[4][4];
                #pragma unroll
                for (int pr = 0; pr < 4; pr++) {
                    const int n  = wcol + pr * 16 + (mat >> 1) * 8 + mrow;
                    const int kk = ks * 16 + (mat & 1) * 8;
                    ldsm_x4(bfr[pr], wb + woff(n, kk));
                }
                #pragma unroll
                for (int hv = 0; hv < 2; hv++) {   // 0: Xhi, 1: Xlo
                    uint32_t afr[2][4];
                    #pragma unroll
                    for (int mt = 0; mt < 2; mt++) {
                        const int row = wrow + mt * 16 + (mat & 1) * 8 + mrow;
                        const int kk  = ks * 16 + hv * 128 + (mat >> 1) * 8;
                        ldsm_x4(afr[mt], xb + soff(row, kk));
                    }
                    #pragma unroll
                    for (int pr = 0; pr < 4; pr++) {
                        #pragma unroll
                        for (int mt = 0; mt < 2; mt++) {
                            mma16816(acc[mt][2 * pr],     afr[mt], bfr[pr]);
                            mma16816(acc[mt][2 * pr + 1], afr[mt], bfr[pr] + 2);
                        }
                    }
                }
            }

            if (layer == 0) {
                __syncthreads();   // all warps done reading X
                // bias + ELU -> exact fp16 split back into X as layer-2 A
                const float* b1s = (const float*)(sm + SM_B1);
                #pragma unroll
                for (int mt = 0; mt < 2; mt++) {
                    const int r0 = wrow + mt * 16 + (lane >> 2);
                    #pragma unroll
                    for (int nt = 0; nt < 8; nt++) {
                        const int c  = wcol + nt * 8 + (lane & 3) * 2;
                        const float bb0 = b1s[c], bb1 = b1s[c + 1];
                        float e0 = elu_f(acc[mt][nt][0] + bb0);
                        float e1 = elu_f(acc[mt][nt][1] + bb1);
                        float e2 = elu_f(acc[mt][nt][2] + bb0);
                        float e3 = elu_f(acc[mt][nt][3] + bb1);
                        uint32_t h0, l0, h1, l1;
                        split_h2(e0, e1, h0, l0);
                        split_h2(e2, e3, h1, l1);
                        *(uint32_t*)(sm + SM_X + soff(r0, c))           = h0;
                        *(uint32_t*)(sm + SM_X + soff(r0, c + 128))     = l0;
                        *(uint32_t*)(sm + SM_X + soff(r0 + 8, c))       = h1;
                        *(uint32_t*)(sm + SM_X + soff(r0 + 8, c + 128)) = l1;
                        acc[mt][nt][0] = 0.0f; acc[mt][nt][1] = 0.0f;
                        acc[mt][nt][2] = 0.0f; acc[mt][nt][3] = 0.0f;
                    }
                }
                __syncthreads();
            }
        }

        // ---- epilogue 2: bias + ELU + weighted 16-row reduce via shuffles ----
        {
            const float* b2s  = (const float*)(sm + SM_B2);
            const float* roww = (const float*)(sm + SM_ROWW);
            #pragma unroll
            for (int mt = 0; mt < 2; mt++) {
                const int q  = (wrow >> 4) + mt;          // query in [0,8)
                const int r0 = wrow + mt * 16 + (lane >> 2);
                const float w0 = roww[r0], w1 = roww[r0 + 8];
                #pragma unroll
                for (int nt = 0; nt < 8; nt++) {
                    const int c  = wcol + nt * 8 + (lane & 3) * 2;
                    const float bb0 = b2s[c], bb1 = b2s[c + 1];
                    float s0 = w0 * elu_f(acc[mt][nt][0] + bb0)
                             + w1 * elu_f(acc[mt][nt][2] + bb0);
                    float s1 = w0 * elu_f(acc[mt][nt][1] + bb1)
                             + w1 * elu_f(acc[mt][nt][3] + bb1);
                    s0 += __shfl_xor_sync(0xFFFFFFFFu, s0, 4);
                    s1 += __shfl_xor_sync(0xFFFFFFFFu, s1, 4);
                    s0 += __shfl_xor_sync(0xFFFFFFFFu, s0, 8);
                    s1 += __shfl_xor_sync(0xFFFFFFFFu, s1, 8);
                    s0 += __shfl_xor_sync(0xFFFFFFFFu, s0, 16);
                    s1 += __shfl_xor_sync(0xFFFFFFFFu, s1, 16);
                    if ((lane >> 2) == 0) {
                        float2 o2 = make_float2(s0, s1);
                        *(float2*)&out[(size_t)(qbase + q) * 128 + c] = o2;
                    }
                }
            }
        }
    }
}

extern "C" void kernel_launch(void* const* d_in, const int* in_sizes, int n_in,
                              void* d_out, int out_size) {
    const float* f1     = (const float*)d_in[0];
    const float* f2     = (const float*)d_in[1];
    const float* x1     = (const float*)d_in[2];
    const float* x2     = (const float*)d_in[3];
    const void*  topk   = d_in[6];
    const float* W1     = (const float*)d_in[7];
    const float* b1     = (const float*)d_in[8];
    const float* W2     = (const float*)d_in[9];
    const float* b2     = (const float*)d_in[10];
    const float* radius = (const float*)d_in[11];
    float* out = (float*)d_out;

    prep_w_kernel<<<128, 256>>>(W1, W2);

    cudaFuncSetAttribute(fused_mma_kernel,
                         cudaFuncAttributeMaxDynamicSharedMemorySize, SM_TOTAL);
    fused_mma_kernel<<<kGrid, kThreads, SM_TOTAL>>>(
        f1, f2, x1, x2, topk, b1, b2, radius, out);
}

// round 8
// speedup vs baseline: 1.1506x; 1.1506x over previous
#include <cuda_runtime.h>
#include <cuda_fp16.h>
#include <cstdint>

// fp16 2-pass "exact-A" tensor-core version, 512 threads/CTA: two independent
// 128-row tiles per CTA iteration (half 0 = warps 0-7, half 1 = warps 8-15),
// sharing W in smem, synchronized via per-half named barriers so the halves
// overlap each other's gather/epilogue with MMA.
//   X[128x128] = [features2[topk] | features1]  (8 queries x 16 nbrs = 128 rows)
//   H = ELU(X@W1+b1); Y = ELU(H@W2+b2); out[q] = sum_k w[q,k] * Y[q*16+k]
// GEMM: D(fp32) = Xh*Wh + Xl*Wh = X*Wh  (A exact; err = W fp16 rounding)

namespace {
constexpr int kN1      = 50000;
constexpr int kNN      = 16;
constexpr int kQPB     = 8;               // queries per 128-row tile
constexpr int kSuper   = kN1 / (2 * kQPB); // 3125 CTA iterations (2 tiles each)
constexpr int kThreads = 512;
constexpr int kGrid    = 148;

// SMEM byte offsets
constexpr int SM_ROWW  = 0;                     // 2 halves x 128 f32
constexpr int SM_B1    = 1024;                  // 128 f32
constexpr int SM_B2    = 1536;                  // 128 f32
constexpr int SM_X     = 2048;                  // 2 halves x 65536 B
constexpr int SM_XHSZ  = 65536;                 // per-half X (128 rows x 256 fp16)
constexpr int SM_W     = SM_X + 2 * SM_XHSZ;    // 133120
constexpr int SM_WSZ   = 32768;                 // per-layer W
constexpr int SM_TOTAL = SM_W + 2 * SM_WSZ;     // 198656 B
}

// fp16 weights, transposed+swizzled: [W1, W2], each [n][k]
__device__ __align__(16) unsigned char g_Wh[2 * SM_WSZ];

// X tile: row stride 512 B, XOR swizzle on 16B groups
__device__ __forceinline__ uint32_t soff(int r, int kk) {
    return (uint32_t)(r * 512 + (((kk >> 3) ^ (r & 7)) << 4) + (kk & 7) * 2);
}
// W tile: row stride 256 B
__device__ __forceinline__ uint32_t woff(int n, int k) {
    return (uint32_t)(n * 256 + (((k >> 3) ^ (n & 7)) << 4) + (k & 7) * 2);
}

__device__ __forceinline__ uint32_t smem_u32(const void* p) {
    uint32_t a;
    asm("{ .reg .u64 t; cvta.to.shared.u64 t, %1; cvt.u32.u64 %0, t; }"
        : "=r"(a) : "l"(p));
    return a;
}
__device__ __forceinline__ void ldsm_x4(uint32_t* r, uint32_t addr) {
    asm volatile("ldmatrix.sync.aligned.m8n8.x4.shared.b16 {%0,%1,%2,%3}, [%4];"
                 : "=r"(r[0]), "=r"(r[1]), "=r"(r[2]), "=r"(r[3]) : "r"(addr));
}
__device__ __forceinline__ void mma16816(float* d, const uint32_t* a,
                                         const uint32_t* b) {
    asm volatile(
        "mma.sync.aligned.m16n8k16.row.col.f32.f16.f16.f32 "
        "{%0,%1,%2,%3}, {%4,%5,%6,%7}, {%8,%9}, {%0,%1,%2,%3};"
        : "+f"(d[0]), "+f"(d[1]), "+f"(d[2]), "+f"(d[3])
        : "r"(a[0]), "r"(a[1]), "r"(a[2]), "r"(a[3]), "r"(b[0]), "r"(b[1]));
}
__device__ __forceinline__ void barh(int id) {
    asm volatile("bar.sync %0, 256;" :: "r"(id) : "memory");
}
__device__ __forceinline__ float elu_f(float x) {
    return x > 0.0f ? x : (__expf(x) - 1.0f);
}
// exact fp16 hi/lo split of a float pair -> two packed half2
__device__ __forceinline__ void split_h2(float a, float b, uint32_t& hi,
                                         uint32_t& lo) {
    const __half ah = __float2half_rn(a);
    const __half bh = __float2half_rn(b);
    __half2 h2 = __halves2half2(ah, bh);
    __half2 l2 = __halves2half2(__float2half_rn(a - __half2float(ah)),
                                __float2half_rn(b - __half2float(bh)));
    hi = *(uint32_t*)&h2;
    lo = *(uint32_t*)&l2;
}

// ---------------- W prep kernel ----------------
__global__ void prep_w_kernel(const float* __restrict__ W1,
                              const float* __restrict__ W2) {
    int idx = blockIdx.x * blockDim.x + threadIdx.x;   // 0 .. 32767
    if (idx >= 2 * 128 * 128) return;
    int l = idx >> 14;
    int e = idx & 16383;
    int n = e >> 7;      // output channel (B row)
    int k = e & 127;     // contraction
    const float* W = l ? W2 : W1;
    float v = W[k * 128 + n];                       // B[n][k] = W[k][n]
    *(__half*)(g_Wh + l * SM_WSZ + woff(n, k)) = __float2half_rn(v);
}

// ---------------- main persistent kernel ----------------
__global__ void __launch_bounds__(kThreads, 1)
fused_mma_kernel(const float* __restrict__ f1, const float* __restrict__ f2,
                 const float* __restrict__ x1, const float* __restrict__ x2,
                 const void* __restrict__ topk,
                 const float* __restrict__ b1, const float* __restrict__ b2,
                 const float* __restrict__ radius, float* __restrict__ out)
{
    extern __shared__ char sm[];
    const uint32_t smb = smem_u32(sm);
    const int tid  = threadIdx.x;
    const int lane = tid & 31;
    __shared__ int s_is64;

    // stage fp16 weights into SMEM once
    {
        const float4* src = (const float4*)g_Wh;
        float4* dst = (float4*)(sm + SM_W);
        #pragma unroll
        for (int i = 0; i < 8; i++) dst[tid + i * 512] = src[tid + i * 512];
    }
    if (tid < 128) {
        ((float*)(sm + SM_B1))[tid] = b1[tid];
        ((float*)(sm + SM_B2))[tid] = b2[tid];
    }
    if (tid < 32) {
        const int* t32 = (const int*)topk;
        unsigned m = __ballot_sync(0xFFFFFFFFu, t32[2 * tid + 1] != 0);
        if (tid == 0) s_is64 = (m == 0u) ? 1 : 0;
    }
    __syncthreads();

    const bool  is64 = (s_is64 != 0);
    const float r    = radius[0];
    const float nid  = -1.0f / (2.0f * r * r);

    const int half  = tid >> 8;            // 0: warps 0-7, 1: warps 8-15
    const int tid_h = tid & 255;
    const int hwid  = (tid >> 5) & 7;
    const int barid = 1 + half;

    const int wrow = (hwid & 3) * 32;      // warp tile rows [wrow, wrow+32)
    const int wcol = (hwid >> 2) * 64;     // warp tile cols [wcol, wcol+64)
    const int mat  = lane >> 3;            // ldmatrix sub-matrix index
    const int mrow = lane & 7;

    char* xB = sm + SM_X + half * SM_XHSZ;
    const uint32_t xb = smb + SM_X + half * SM_XHSZ;
    float* roww = (float*)(sm + SM_ROWW) + half * 128;

    for (int s = blockIdx.x; s < kSuper; s += gridDim.x) {
        const int qbase = (2 * s + half) * kQPB;

        barh(barid);   // this half's prev layer-2 MMA done: X safe to overwrite

        // ---- gather + exact fp16 split into Xhi/Xlo ----
        {
            const int g = tid_h & 15;      // 8-float group per row
            #pragma unroll
            for (int it = 0; it < 8; ++it) {
                const int rr = (tid_h >> 4) + it * 16;   // row 0..127
                const int q  = qbase + (rr >> 4);
                const float4* p;
                if (g < 8) {
                    const int nb = rr & 15;
                    const int gi = is64 ? (int)((const long long*)topk)[q * kNN + nb]
                                        : ((const int*)topk)[q * kNN + nb];
                    p = (const float4*)(f2 + (size_t)gi * 64) + g * 2;
                } else {
                    p = (const float4*)(f1 + (size_t)q * 64) + (g - 8) * 2;
                }
                const float4 v0 = p[0], v1 = p[1];
                const float v[8] = {v0.x, v0.y, v0.z, v0.w, v1.x, v1.y, v1.z, v1.w};
                uint4 hi4, lo4;
                uint32_t* hp = (uint32_t*)&hi4;
                uint32_t* lp = (uint32_t*)&lo4;
                #pragma unroll
                for (int j = 0; j < 4; j++)
                    split_h2(v[2 * j], v[2 * j + 1], hp[j], lp[j]);
                *(uint4*)(xB + soff(rr, g * 8))       = hi4;
                *(uint4*)(xB + soff(rr, g * 8 + 128)) = lo4;
            }
        }
        // ---- per-row distance weights ----
        if (tid_h < 128) {
            const int q  = qbase + (tid_h >> 4);
            const int kk = tid_h & 15;
            int gi = is64 ? (int)((const long long*)topk)[q * kNN + kk]
                          : ((const int*)topk)[q * kNN + kk];
            const float dx = x2[gi * 3 + 0] - x1[q * 3 + 0];
            const float dy = x2[gi * 3 + 1] - x1[q * 3 + 1];
            const float dz = x2[gi * 3 + 2] - x1[q * 3 + 2];
            const float w  = __expf(nid * (dx * dx + dy * dy + dz * dz));
            roww[tid_h] = (gi == 0) ? 0.0f : w;
        }
        barh(barid);

        float acc[2][8][4];
        #pragma unroll
        for (int i = 0; i < 2; i++)
            #pragma unroll
            for (int j = 0; j < 8; j++)
                #pragma unroll
                for (int e = 0; e < 4; e++) acc[i][j][e] = 0.0f;

        #pragma unroll 1
        for (int layer = 0; layer < 2; ++layer) {
            const uint32_t wb = smb + SM_W + layer * SM_WSZ;

            #pragma unroll 1
            for (int ks = 0; ks < 8; ++ks) {
                // B fragments once per ks, reused by both A halves
                uint32_t bfr[4][4];
                #pragma unroll
                for (int pr = 0; pr < 4; pr++) {
                    const int n  = wcol + pr * 16 + (mat >> 1) * 8 + mrow;
                    const int kk = ks * 16 + (mat & 1) * 8;
                    ldsm_x4(bfr[pr], wb + woff(n, kk));
                }
                #pragma unroll
                for (int hv = 0; hv < 2; hv++) {   // 0: Xhi, 1: Xlo
                    uint32_t afr[2][4];
                    #pragma unroll
                    for (int mt = 0; mt < 2; mt++) {
                        const int row = wrow + mt * 16 + (mat & 1) * 8 + mrow;
                        const int kk  = ks * 16 + hv * 128 + (mat >> 1) * 8;
                        ldsm_x4(afr[mt], xb + soff(row, kk));
                    }
                    #pragma unroll
                    for (int pr = 0; pr < 4; pr++) {
                        #pragma unroll
                        for (int mt = 0; mt < 2; mt++) {
                            mma16816(acc[mt][2 * pr],     afr[mt], bfr[pr]);
                            mma16816(acc[mt][2 * pr + 1], afr[mt], bfr[pr] + 2);
                        }
                    }
                }
            }

            if (layer == 0) {
                barh(barid);   // this half's warps done reading X
                // bias + ELU -> exact fp16 split back into X as layer-2 A
                const float* b1s = (const float*)(sm + SM_B1);
                #pragma unroll
                for (int mt = 0; mt < 2; mt++) {
                    const int r0 = wrow + mt * 16 + (lane >> 2);
                    #pragma unroll
                    for (int nt = 0; nt < 8; nt++) {
                        const int c  = wcol + nt * 8 + (lane & 3) * 2;
                        const float bb0 = b1s[c], bb1 = b1s[c + 1];
                        float e0 = elu_f(acc[mt][nt][0] + bb0);
                        float e1 = elu_f(acc[mt][nt][1] + bb1);
                        float e2 = elu_f(acc[mt][nt][2] + bb0);
                        float e3 = elu_f(acc[mt][nt][3] + bb1);
                        uint32_t h0, l0, h1, l1;
                        split_h2(e0, e1, h0, l0);
                        split_h2(e2, e3, h1, l1);
                        *(uint32_t*)(xB + soff(r0, c))           = h0;
                        *(uint32_t*)(xB + soff(r0, c + 128))     = l0;
                        *(uint32_t*)(xB + soff(r0 + 8, c))       = h1;
                        *(uint32_t*)(xB + soff(r0 + 8, c + 128)) = l1;
                        acc[mt][nt][0] = 0.0f; acc[mt][nt][1] = 0.0f;
                        acc[mt][nt][2] = 0.0f; acc[mt][nt][3] = 0.0f;
                    }
                }
                barh(barid);
            }
        }

        // ---- epilogue 2: bias + ELU + weighted 16-row reduce via shuffles ----
        {
            const float* b2s = (const float*)(sm + SM_B2);
            #pragma unroll
            for (int mt = 0; mt < 2; mt++) {
                const int q  = (wrow >> 4) + mt;          // query in [0,8)
                const int r0 = wrow + mt * 16 + (lane >> 2);
                const float w0 = roww[r0], w1 = roww[r0 + 8];
                #pragma unroll
                for (int nt = 0; nt < 8; nt++) {
                    const int c  = wcol + nt * 8 + (lane & 3) * 2;
                    const float bb0 = b2s[c], bb1 = b2s[c + 1];
                    float s0 = w0 * elu_f(acc[mt][nt][0] + bb0)
                             + w1 * elu_f(acc[mt][nt][2] + bb0);
                    float s1 = w0 * elu_f(acc[mt][nt][1] + bb1)
                             + w1 * elu_f(acc[mt][nt][3] + bb1);
                    s0 += __shfl_xor_sync(0xFFFFFFFFu, s0, 4);
                    s1 += __shfl_xor_sync(0xFFFFFFFFu, s1, 4);
                    s0 += __shfl_xor_sync(0xFFFFFFFFu, s0, 8);
                    s1 += __shfl_xor_sync(0xFFFFFFFFu, s1, 8);
                    s0 += __shfl_xor_sync(0xFFFFFFFFu, s0, 16);
                    s1 += __shfl_xor_sync(0xFFFFFFFFu, s1, 16);
                    if ((lane >> 2) == 0) {
                        float2 o2 = make_float2(s0, s1);
                        *(float2*)&out[(size_t)(qbase + q) * 128 + c] = o2;
                    }
                }
            }
        }
    }
}

extern "C" void kernel_launch(void* const* d_in, const int* in_sizes, int n_in,
                              void* d_out, int out_size) {
    const float* f1     = (const float*)d_in[0];
    const float* f2     = (const float*)d_in[1];
    const float* x1     = (const float*)d_in[2];
    const float* x2     = (const float*)d_in[3];
    const void*  topk   = d_in[6];
    const float* W1     = (const float*)d_in[7];
    const float* b1     = (const float*)d_in[8];
    const float* W2     = (const float*)d_in[9];
    const float* b2     = (const float*)d_in[10];
    const float* radius = (const float*)d_in[11];
    float* out = (float*)d_out;

    prep_w_kernel<<<128, 256>>>(W1, W2);

    cudaFuncSetAttribute(fused_mma_kernel,
                         cudaFuncAttributeMaxDynamicSharedMemorySize, SM_TOTAL);
    fused_mma_kernel<<<kGrid, kThreads, SM_TOTAL>>>(
        f1, f2, x1, x2, topk, b1, b2, radius, out);
}

// round 9
// speedup vs baseline: 2.0134x; 1.7498x over previous
#include <cuda_runtime.h>
#include <cuda_fp16.h>
#include <cstdint>

// Algebraic split: layer 1 is precomputed per-point, not per-pair.
//   G2 = f2 @ W1[0:64,:]          (50000 x 128, fp32, device global)
//   G1 = f1 @ W1[64:128,:] + b1   (50000 x 128, fp32, device global)
//   per tile: A = fp16(ELU(G2[topk] + G1[q]))  -> one 128x128x128 fp16 MMA GEMM
//   out[q] = sum_k w[q,k] * ELU(A@W2 + b2)
// Layer-2 GEMM is 1-pass fp16 (A and W2 rounded); precompute GEMM is
// 2-pass exact-A fp16 (error = W1 rounding only).

namespace {
constexpr int kN1      = 50000;
constexpr int kNN      = 16;
constexpr int kQPB     = 8;                // queries per 128-row tile
constexpr int kSuper   = kN1 / (2 * kQPB); // 3125 CTA iterations (2 tiles each)
constexpr int kThreads = 512;
constexpr int kGrid    = 148;
constexpr int kNPad    = 50048;            // padded row count for G arrays

// main kernel smem
constexpr int SM_ROWW  = 0;                    // 2 halves x 128 f32
constexpr int SM_B2    = 1024;                 // 128 f32
constexpr int SM_X     = 2048;                 // 2 halves x 32768 B (fp16 128x128)
constexpr int SM_XHSZ  = 32768;
constexpr int SM_W     = SM_X + 2 * SM_XHSZ;   // 67584
constexpr int SM_TOTAL = SM_W + 32768;         // 100352 B

// precompute kernel smem
constexpr int PP_A     = 0;        // 32768 B: A hi (kk 0..63) | lo (kk 64..127)
constexpr int PP_W     = 32768;    // 32768 B: W1 part, k-padded to 128
constexpr int PP_TOTAL = 65536;
}

__device__ __align__(16) unsigned char g_W2h[32768];      // W2^T fp16 swizzled
__device__ __align__(16) unsigned char g_W1h[2][32768];   // W1 halves^T fp16 (k-padded)
__device__ float g_G2[(size_t)kNPad * 128];
__device__ float g_G1[(size_t)kNPad * 128];

// [n][k] fp16 tile, 256 B per row, XOR swizzle on 16B groups
__device__ __forceinline__ uint32_t woff(int n, int k) {
    return (uint32_t)(n * 256 + ((((k >> 3) ^ (n & 7)) & 15) << 4) + (k & 7) * 2);
}

__device__ __forceinline__ uint32_t smem_u32(const void* p) {
    uint32_t a;
    asm("{ .reg .u64 t; cvta.to.shared.u64 t, %1; cvt.u32.u64 %0, t; }"
        : "=r"(a) : "l"(p));
    return a;
}
__device__ __forceinline__ void ldsm_x4(uint32_t* r, uint32_t addr) {
    asm volatile("ldmatrix.sync.aligned.m8n8.x4.shared.b16 {%0,%1,%2,%3}, [%4];"
                 : "=r"(r[0]), "=r"(r[1]), "=r"(r[2]), "=r"(r[3]) : "r"(addr));
}
__device__ __forceinline__ void mma16816(float* d, const uint32_t* a,
                                         const uint32_t* b) {
    asm volatile(
        "mma.sync.aligned.m16n8k16.row.col.f32.f16.f16.f32 "
        "{%0,%1,%2,%3}, {%4,%5,%6,%7}, {%8,%9}, {%0,%1,%2,%3};"
        : "+f"(d[0]), "+f"(d[1]), "+f"(d[2]), "+f"(d[3])
        : "r"(a[0]), "r"(a[1]), "r"(a[2]), "r"(a[3]), "r"(b[0]), "r"(b[1]));
}
__device__ __forceinline__ void barh(int id) {
    asm volatile("bar.sync %0, 256;" :: "r"(id) : "memory");
}
__device__ __forceinline__ float elu_f(float x) {
    return x > 0.0f ? x : (__expf(x) - 1.0f);
}
__device__ __forceinline__ void split_h2(float a, float b, uint32_t& hi,
                                         uint32_t& lo) {
    const __half ah = __float2half_rn(a);
    const __half bh = __float2half_rn(b);
    __half2 h2 = __halves2half2(ah, bh);
    __half2 l2 = __halves2half2(__float2half_rn(a - __half2float(ah)),
                                __float2half_rn(b - __half2float(bh)));
    hi = *(uint32_t*)&h2;
    lo = *(uint32_t*)&l2;
}

// ---------------- W prep kernel ----------------
__global__ void prep_w_kernel(const float* __restrict__ W1,
                              const float* __restrict__ W2) {
    int idx = blockIdx.x * blockDim.x + threadIdx.x;   // 0 .. 49151
    if (idx >= 3 * 128 * 128) return;
    int sec = idx >> 14;
    int e = idx & 16383;
    int n = e >> 7;      // output channel (B row)
    int k = e & 127;     // contraction
    if (sec == 0) {
        *(__half*)(g_W2h + woff(n, k)) = __float2half_rn(W2[k * 128 + n]);
    } else {
        int p = sec - 1;                 // 0: W1 rows 0..63 (f2), 1: rows 64..127 (f1)
        float v = (k < 64) ? W1[(k + 64 * p) * 128 + n] : 0.0f;
        *(__half*)(g_W1h[p] + woff(n, k)) = __float2half_rn(v);
    }
}

// ---------------- precompute kernel: G2 / G1 ----------------
__global__ void __launch_bounds__(256, 1)
precompute_kernel(const float* __restrict__ f1, const float* __restrict__ f2,
                  const float* __restrict__ b1) {
    extern __shared__ char sm[];
    const uint32_t smb = smem_u32(sm);
    const int which = blockIdx.y;             // 0 -> G2 (f2), 1 -> G1 (f1, +b1)
    const float* f = which ? f1 : f2;
    float* G = which ? g_G1 : g_G2;
    const int tid  = threadIdx.x;
    const int lane = tid & 31;
    const int wid  = tid >> 5;
    const int row0 = blockIdx.x * 128;

    // stage W1 part (fp16, k-padded) into smem
    {
        const float4* src = (const float4*)g_W1h[which];
        float4* dst = (float4*)(sm + PP_W);
        #pragma unroll
        for (int i = 0; i < 8; i++) dst[tid + i * 256] = src[tid + i * 256];
    }
    // load features, exact fp16 split: hi at kk 0..63, lo at kk 64..127
    {
        #pragma unroll
        for (int it = 0; it < 4; ++it) {
            const int rr = (tid >> 3) + it * 32;       // row 0..127
            const int g  = tid & 7;                    // 8-float group
            const int grow = min(row0 + rr, kN1 - 1);
            const float4* p = (const float4*)(f + (size_t)grow * 64) + g * 2;
            const float4 v0 = p[0], v1 = p[1];
            const float v[8] = {v0.x, v0.y, v0.z, v0.w, v1.x, v1.y, v1.z, v1.w};
            uint4 hi4, lo4;
            uint32_t* hp = (uint32_t*)&hi4;
            uint32_t* lp = (uint32_t*)&lo4;
            #pragma unroll
            for (int j = 0; j < 4; j++)
                split_h2(v[2 * j], v[2 * j + 1], hp[j], lp[j]);
            *(uint4*)(sm + PP_A + woff(rr, g * 8))      = hi4;
            *(uint4*)(sm + PP_A + woff(rr, g * 8 + 64)) = lo4;
        }
    }
    __syncthreads();

    const int wrow = (wid & 3) * 32;
    const int wcol = (wid >> 2) * 64;
    const int mat  = lane >> 3;
    const int mrow = lane & 7;

    float acc[2][8][4];
    #pragma unroll
    for (int i = 0; i < 2; i++)
        #pragma unroll
        for (int j = 0; j < 8; j++)
            #pragma unroll
            for (int e = 0; e < 4; e++) acc[i][j][e] = 0.0f;

    #pragma unroll
    for (int ks = 0; ks < 4; ++ks) {
        uint32_t bfr[4][4];
        #pragma unroll
        for (int pr = 0; pr < 4; pr++) {
            const int n  = wcol + pr * 16 + (mat >> 1) * 8 + mrow;
            const int kk = ks * 16 + (mat & 1) * 8;
            ldsm_x4(bfr[pr], smb + PP_W + woff(n, kk));
        }
        #pragma unroll
        for (int hv = 0; hv < 2; hv++) {
            uint32_t afr[2][4];
            #pragma unroll
            for (int mt = 0; mt < 2; mt++) {
                const int row = wrow + mt * 16 + (mat & 1) * 8 + mrow;
                const int kk  = ks * 16 + hv * 64 + (mat >> 1) * 8;
                ldsm_x4(afr[mt], smb + PP_A + woff(row, kk));
            }
            #pragma unroll
            for (int pr = 0; pr < 4; pr++) {
                #pragma unroll
                for (int mt = 0; mt < 2; mt++) {
                    mma16816(acc[mt][2 * pr],     afr[mt], bfr[pr]);
                    mma16816(acc[mt][2 * pr + 1], afr[mt], bfr[pr] + 2);
                }
            }
        }
    }

    // store fp32 (+b1 for G1)
    #pragma unroll
    for (int mt = 0; mt < 2; mt++) {
        const int r0 = wrow + mt * 16 + (lane >> 2);
        #pragma unroll
        for (int nt = 0; nt < 8; nt++) {
            const int c = wcol + nt * 8 + (lane & 3) * 2;
            const float bb0 = which ? b1[c] : 0.0f;
            const float bb1 = which ? b1[c + 1] : 0.0f;
            const int ga = row0 + r0, gb = row0 + r0 + 8;
            if (ga < kN1)
                *(float2*)&G[(size_t)ga * 128 + c] =
                    make_float2(acc[mt][nt][0] + bb0, acc[mt][nt][1] + bb1);
            if (gb < kN1)
                *(float2*)&G[(size_t)gb * 128 + c] =
                    make_float2(acc[mt][nt][2] + bb0, acc[mt][nt][3] + bb1);
        }
    }
}

// ---------------- main persistent kernel ----------------
__global__ void __launch_bounds__(kThreads, 1)
fused_mma_kernel(const float* __restrict__ x1, const float* __restrict__ x2,
                 const void* __restrict__ topk,
                 const float* __restrict__ b2,
                 const float* __restrict__ radius, float* __restrict__ out)
{
    extern __shared__ char sm[];
    const uint32_t smb = smem_u32(sm);
    const int tid  = threadIdx.x;
    const int lane = tid & 31;
    __shared__ int s_is64;

    // stage fp16 W2 into smem once
    {
        const float4* src = (const float4*)g_W2h;
        float4* dst = (float4*)(sm + SM_W);
        #pragma unroll
        for (int i = 0; i < 4; i++) dst[tid + i * 512] = src[tid + i * 512];
    }
    if (tid < 128) ((float*)(sm + SM_B2))[tid] = b2[tid];
    if (tid < 32) {
        const int* t32 = (const int*)topk;
        unsigned m = __ballot_sync(0xFFFFFFFFu, t32[2 * tid + 1] != 0);
        if (tid == 0) s_is64 = (m == 0u) ? 1 : 0;
    }
    __syncthreads();

    const bool  is64 = (s_is64 != 0);
    const float r    = radius[0];
    const float nid  = -1.0f / (2.0f * r * r);

    const int half  = tid >> 8;            // 0: warps 0-7, 1: warps 8-15
    const int tid_h = tid & 255;
    const int hwid  = (tid >> 5) & 7;
    const int barid = 1 + half;

    const int wrow = (hwid & 3) * 32;
    const int wcol = (hwid >> 2) * 64;
    const int mat  = lane >> 3;
    const int mrow = lane & 7;

    char* xB = sm + SM_X + half * SM_XHSZ;
    const uint32_t xb = smb + SM_X + half * SM_XHSZ;
    float* roww = (float*)(sm + SM_ROWW) + half * 128;

    for (int s = blockIdx.x; s < kSuper; s += gridDim.x) {
        const int qbase = (2 * s + half) * kQPB;

        barh(barid);   // this half's prev MMA done: X safe to overwrite

        // ---- layer 1: gather G2[gi] + G1[q], ELU, cvt fp16 -> X ----
        {
            const int g = tid_h & 15;      // 8-float group per row
            #pragma unroll
            for (int it = 0; it < 8; ++it) {
                const int rr = (tid_h >> 4) + it * 16;   // row 0..127
                const int q  = qbase + (rr >> 4);
                const int nb = rr & 15;
                const int gi = is64 ? (int)((const long long*)topk)[q * kNN + nb]
                                    : ((const int*)topk)[q * kNN + nb];
                const float4* pg = (const float4*)(g_G2 + (size_t)gi * 128) + g * 2;
                const float4* pq = (const float4*)(g_G1 + (size_t)q * 128) + g * 2;
                const float4 a0 = pg[0], a1 = pg[1];
                const float4 c0 = pq[0], c1 = pq[1];
                const float v[8] = {a0.x + c0.x, a0.y + c0.y, a0.z + c0.z, a0.w + c0.w,
                                    a1.x + c1.x, a1.y + c1.y, a1.z + c1.z, a1.w + c1.w};
                uint4 h4;
                uint32_t* hp = (uint32_t*)&h4;
                #pragma unroll
                for (int j = 0; j < 4; j++) {
                    __half2 p2 = __halves2half2(
                        __float2half_rn(elu_f(v[2 * j])),
                        __float2half_rn(elu_f(v[2 * j + 1])));
                    hp[j] = *(uint32_t*)&p2;
                }
                *(uint4*)(xB + woff(rr, g * 8)) = h4;
            }
        }
        // ---- per-row distance weights ----
        if (tid_h < 128) {
            const int q  = qbase + (tid_h >> 4);
            const int kk = tid_h & 15;
            int gi = is64 ? (int)((const long long*)topk)[q * kNN + kk]
                          : ((const int*)topk)[q * kNN + kk];
            const float dx = x2[gi * 3 + 0] - x1[q * 3 + 0];
            const float dy = x2[gi * 3 + 1] - x1[q * 3 + 1];
            const float dz = x2[gi * 3 + 2] - x1[q * 3 + 2];
            const float w  = __expf(nid * (dx * dx + dy * dy + dz * dz));
            roww[tid_h] = (gi == 0) ? 0.0f : w;
        }
        barh(barid);

        // ---- layer 2 GEMM: 1-pass fp16 ----
        float acc[2][8][4];
        #pragma unroll
        for (int i = 0; i < 2; i++)
            #pragma unroll
            for (int j = 0; j < 8; j++)
                #pragma unroll
                for (int e = 0; e < 4; e++) acc[i][j][e] = 0.0f;

        const uint32_t wb = smb + SM_W;
        #pragma unroll 1
        for (int ks = 0; ks < 8; ++ks) {
            uint32_t bfr[4][4];
            #pragma unroll
            for (int pr = 0; pr < 4; pr++) {
                const int n  = wcol + pr * 16 + (mat >> 1) * 8 + mrow;
                const int kk = ks * 16 + (mat & 1) * 8;
                ldsm_x4(bfr[pr], wb + woff(n, kk));
            }
            uint32_t afr[2][4];
            #pragma unroll
            for (int mt = 0; mt < 2; mt++) {
                const int row = wrow + mt * 16 + (mat & 1) * 8 + mrow;
                const int kk  = ks * 16 + (mat >> 1) * 8;
                ldsm_x4(afr[mt], xb + woff(row, kk));
            }
            #pragma unroll
            for (int pr = 0; pr < 4; pr++) {
                #pragma unroll
                for (int mt = 0; mt < 2; mt++) {
                    mma16816(acc[mt][2 * pr],     afr[mt], bfr[pr]);
                    mma16816(acc[mt][2 * pr + 1], afr[mt], bfr[pr] + 2);
                }
            }
        }

        // ---- epilogue: bias + ELU + weighted 16-row reduce via shuffles ----
        {
            const float* b2s = (const float*)(sm + SM_B2);
            #pragma unroll
            for (int mt = 0; mt < 2; mt++) {
                const int q  = (wrow >> 4) + mt;          // query in [0,8)
                const int r0 = wrow + mt * 16 + (lane >> 2);
                const float w0 = roww[r0], w1 = roww[r0 + 8];
                #pragma unroll
                for (int nt = 0; nt < 8; nt++) {
                    const int c  = wcol + nt * 8 + (lane & 3) * 2;
                    const float bb0 = b2s[c], bb1 = b2s[c + 1];
                    float s0 = w0 * elu_f(acc[mt][nt][0] + bb0)
                             + w1 * elu_f(acc[mt][nt][2] + bb0);
                    float s1 = w0 * elu_f(acc[mt][nt][1] + bb1)
                             + w1 * elu_f(acc[mt][nt][3] + bb1);
                    s0 += __shfl_xor_sync(0xFFFFFFFFu, s0, 4);
                    s1 += __shfl_xor_sync(0xFFFFFFFFu, s1, 4);
                    s0 += __shfl_xor_sync(0xFFFFFFFFu, s0, 8);
                    s1 += __shfl_xor_sync(0xFFFFFFFFu, s1, 8);
                    s0 += __shfl_xor_sync(0xFFFFFFFFu, s0, 16);
                    s1 += __shfl_xor_sync(0xFFFFFFFFu, s1, 16);
                    if ((lane >> 2) == 0) {
                        *(float2*)&out[(size_t)(qbase + q) * 128 + c] =
                            make_float2(s0, s1);
                    }
                }
            }
        }
    }
}

extern "C" void kernel_launch(void* const* d_in, const int* in_sizes, int n_in,
                              void* d_out, int out_size) {
    const float* f1     = (const float*)d_in[0];
    const float* f2     = (const float*)d_in[1];
    const float* x1     = (const float*)d_in[2];
    const float* x2     = (const float*)d_in[3];
    const void*  topk   = d_in[6];
    const float* W1     = (const float*)d_in[7];
    const float* b1     = (const float*)d_in[8];
    const float* W2     = (const float*)d_in[9];
    const float* b2     = (const float*)d_in[10];
    const float* radius = (const float*)d_in[11];
    float* out = (float*)d_out;

    prep_w_kernel<<<192, 256>>>(W1, W2);

    cudaFuncSetAttribute(precompute_kernel,
                         cudaFuncAttributeMaxDynamicSharedMemorySize, PP_TOTAL);
    precompute_kernel<<<dim3((kN1 + 127) / 128, 2), 256, PP_TOTAL>>>(f1, f2, b1);

    cudaFuncSetAttribute(fused_mma_kernel,
                         cudaFuncAttributeMaxDynamicSharedMemorySize, SM_TOTAL);
    fused_mma_kernel<<<kGrid, kThreads, SM_TOTAL>>>(
        x1, x2, topk, b2, radius, out);
}